// round 1
// baseline (speedup 1.0000x reference)
#include <cuda_runtime.h>

// ---------------------------------------------------------------------------
// Seq2seq LSTM: encoder (48 steps, C_IN=16) -> decoder (24 steps, zero input)
// -> per-timestep dense H->8.  N=8192, H=256, 4H=1024.
//
// Strategy: batch-parallel persistent CTAs. Each CTA owns 64 samples and runs
// the full recurrence with h (double-buffered) and c in SMEM. Weights are
// pre-transposed to k-major in __device__ scratch so the inner-loop weight
// loads are coalesced across lanes (lane = hidden index k_h). Gate dot
// products use packed fp32x2 FMA (fma.rn.f32x2) over sample pairs.
// ---------------------------------------------------------------------------

#define T_IN   48
#define T_OUT  24
#define C_IN   16
#define C_OUT  8
#define HID    256
#define H4     1024
#define NBATCH 8192

#define NXT (T_IN * C_IN * NBATCH)      // transposed x: [t][c][n]

__device__ float g_xT[NXT];             // ~25 MB scratch
__device__ float g_WihT[C_IN * H4];     // [c][col]   col = gate*256 + k_h
__device__ float g_WhhTe[HID * H4];     // [k][col]
__device__ float g_WhhTd[HID * H4];     // [k][col]

typedef unsigned long long ULL;

// ---- packed f32x2 helpers --------------------------------------------------
__device__ __forceinline__ ULL dup2(float w) {
    ULL r; unsigned u = __float_as_uint(w);
    asm("mov.b64 %0, {%1, %2};" : "=l"(r) : "r"(u), "r"(u));
    return r;
}
__device__ __forceinline__ float2 upk(ULL v) {
    unsigned lo, hi;
    asm("mov.b64 {%0, %1}, %2;" : "=r"(lo), "=r"(hi) : "l"(v));
    return make_float2(__uint_as_float(lo), __uint_as_float(hi));
}
__device__ __forceinline__ ULL f2(ULL a, ULL b, ULL c) {
    ULL d;
    asm("fma.rn.f32x2 %0, %1, %2, %3;" : "=l"(d) : "l"(a), "l"(b), "l"(c));
    return d;
}

// ---- activations (branch-free, safe at extremes) ----------------------------
__device__ __forceinline__ float sigf(float x) {
    return __fdividef(1.0f, 1.0f + __expf(-x));
}
__device__ __forceinline__ float tanh_(float x) {
    return 1.0f - __fdividef(2.0f, __expf(2.0f * x) + 1.0f);
}

// ---- layout constants -------------------------------------------------------
constexpr int HS    = 68;           // padded SMEM row stride (16B aligned, low conflict)
constexpr int HBUF  = HID * HS;     // 17408 floats per h/c buffer
constexpr int SMEM_FLOATS = 3 * HBUF + C_IN * 64;
constexpr int SMEM_BYTES  = SMEM_FLOATS * 4;   // 212992 B

// ---------------------------------------------------------------------------
// Prep: transpose x and the recurrent weights (coalesced writes).
// ---------------------------------------------------------------------------
__global__ void prep_kernel(const float* __restrict__ x,
                            const float* __restrict__ Wih,
                            const float* __restrict__ Whhe,
                            const float* __restrict__ Whhd)
{
    const int TOTAL = NXT + C_IN * H4 + 2 * HID * H4;
    for (int i = blockIdx.x * blockDim.x + threadIdx.x; i < TOTAL;
         i += gridDim.x * blockDim.x) {
        if (i < NXT) {
            int t = i / (C_IN * NBATCH);
            int r = i - t * (C_IN * NBATCH);
            int c = r >> 13;            // / 8192
            int n = r & 8191;
            g_xT[i] = x[(n * C_IN + c) * T_IN + t];
        } else if (i < NXT + C_IN * H4) {
            int j = i - NXT;
            int c = j >> 10, col = j & 1023;
            g_WihT[j] = Wih[col * C_IN + c];
        } else if (i < NXT + C_IN * H4 + HID * H4) {
            int j = i - NXT - C_IN * H4;
            int k = j >> 10, col = j & 1023;
            g_WhhTe[j] = Whhe[col * HID + k];
        } else {
            int j = i - NXT - C_IN * H4 - HID * H4;
            int k = j >> 10, col = j & 1023;
            g_WhhTd[j] = Whhd[col * HID + k];
        }
    }
}

// 8 packed FMAs for one gate row against 4 ulonglong2 (16 samples)
#define FMA8(g, q)                                                   \
    acc[g][0] = f2(q, p0.x, acc[g][0]); acc[g][1] = f2(q, p0.y, acc[g][1]); \
    acc[g][2] = f2(q, p1.x, acc[g][2]); acc[g][3] = f2(q, p1.y, acc[g][3]); \
    acc[g][4] = f2(q, p2.x, acc[g][4]); acc[g][5] = f2(q, p2.y, acc[g][5]); \
    acc[g][6] = f2(q, p3.x, acc[g][6]); acc[g][7] = f2(q, p3.y, acc[g][7]);

// ---------------------------------------------------------------------------
// One LSTM half-pass: this thread computes gates for hidden index k_h and
// 16 samples [bn, bn+16), then does the elementwise LSTM update.
// ---------------------------------------------------------------------------
template <bool WITH_X>
__device__ __forceinline__ void lstm_pass(
    const float* __restrict__ wh,      // transposed Whh [k][col]
    const float* __restrict__ bias,    // (4H,)
    const float* __restrict__ hcur, float* __restrict__ hnxt,
    float* __restrict__ cs, const float* __restrict__ xs,
    int k_h, int bn)
{
    ULL acc[4][8];
    {
        ULL bi = dup2(__ldg(bias + k_h));
        ULL bf = dup2(__ldg(bias + 256 + k_h));
        ULL bg = dup2(__ldg(bias + 512 + k_h));
        ULL bo = dup2(__ldg(bias + 768 + k_h));
        #pragma unroll
        for (int i = 0; i < 8; ++i) {
            acc[0][i] = bi; acc[1][i] = bf; acc[2][i] = bg; acc[3][i] = bo;
        }
    }

    if (WITH_X) {
        const float* wr = g_WihT + k_h;
        const float* xr = xs + bn;
        #pragma unroll
        for (int c2 = 0; c2 < C_IN; ++c2) {
            float w0 = wr[0], w1 = wr[256], w2 = wr[512], w3 = wr[768];
            const ulonglong2* xp = reinterpret_cast<const ulonglong2*>(xr);
            ulonglong2 p0 = xp[0], p1 = xp[1], p2 = xp[2], p3 = xp[3];
            ULL q0 = dup2(w0), q1 = dup2(w1), q2 = dup2(w2), q3 = dup2(w3);
            FMA8(0, q0) FMA8(1, q1) FMA8(2, q2) FMA8(3, q3)
            wr += H4; xr += 64;
        }
    }

    const float* wr = wh + k_h;
    const float* hr = hcur + bn;
    #pragma unroll 2
    for (int k = 0; k < HID; ++k) {
        float w0 = __ldg(wr), w1 = __ldg(wr + 256),
              w2 = __ldg(wr + 512), w3 = __ldg(wr + 768);
        const ulonglong2* hp = reinterpret_cast<const ulonglong2*>(hr);
        ulonglong2 p0 = hp[0], p1 = hp[1], p2 = hp[2], p3 = hp[3];
        ULL q0 = dup2(w0), q1 = dup2(w1), q2 = dup2(w2), q3 = dup2(w3);
        FMA8(0, q0) FMA8(1, q1) FMA8(2, q2) FMA8(3, q3)
        wr += H4; hr += HS;
    }

    // elementwise LSTM update (this thread exclusively owns (k_h, n) cells)
    #pragma unroll
    for (int i = 0; i < 8; ++i) {
        float2 vi = upk(acc[0][i]), vf = upk(acc[1][i]);
        float2 vg = upk(acc[2][i]), vo = upk(acc[3][i]);
        int idx = k_h * HS + bn + 2 * i;
        {
            float co = cs[idx];
            float cn = sigf(vf.x) * co + sigf(vi.x) * tanh_(vg.x);
            cs[idx]   = cn;
            hnxt[idx] = sigf(vo.x) * tanh_(cn);
        }
        {
            float co = cs[idx + 1];
            float cn = sigf(vf.y) * co + sigf(vi.y) * tanh_(vg.y);
            cs[idx + 1]   = cn;
            hnxt[idx + 1] = sigf(vo.y) * tanh_(cn);
        }
    }
}

// ---------------------------------------------------------------------------
// Main persistent kernel: 128 CTAs x 512 threads, 64 samples per CTA.
// ---------------------------------------------------------------------------
__global__ void __launch_bounds__(512, 1)
lstm_kernel(const float* __restrict__ enc_b, const float* __restrict__ dec_b,
            const float* __restrict__ dense_W, const float* __restrict__ dense_b,
            float* __restrict__ out)
{
    extern __shared__ float smem[];
    float* hA = smem;
    float* hB = smem + HBUF;
    float* cs = smem + 2 * HBUF;
    float* xs = smem + 3 * HBUF;

    const int tid = threadIdx.x;
    const int k_h = tid & 255;
    const int nh  = tid >> 8;          // 0 or 1: sample half
    const int n0  = blockIdx.x * 64;

    for (int i = tid; i < 3 * HBUF; i += 512) smem[i] = 0.0f;
    __syncthreads();

    float* hcur = hA;
    float* hnxt = hB;

    // -------- encoder --------
    for (int t = 0; t < T_IN; ++t) {
        for (int i = tid; i < C_IN * 64; i += 512)
            xs[i] = g_xT[(t * C_IN + (i >> 6)) * NBATCH + n0 + (i & 63)];
        __syncthreads();
        lstm_pass<true>(g_WhhTe, enc_b, hcur, hnxt, cs, xs, k_h, nh * 32);
        lstm_pass<true>(g_WhhTe, enc_b, hcur, hnxt, cs, xs, k_h, nh * 32 + 16);
        __syncthreads();
        float* tp = hcur; hcur = hnxt; hnxt = tp;
    }

    // decoder starts from (h_enc, c = 0)
    for (int i = tid; i < HBUF; i += 512) cs[i] = 0.0f;
    __syncthreads();

    // -------- decoder + per-timestep dense --------
    const int nl = tid & 63;
    const int oo = tid >> 6;           // 0..7
    for (int t = 0; t < T_OUT; ++t) {
        lstm_pass<false>(g_WhhTd, dec_b, hcur, hnxt, cs, nullptr, k_h, nh * 32);
        lstm_pass<false>(g_WhhTd, dec_b, hcur, hnxt, cs, nullptr, k_h, nh * 32 + 16);
        __syncthreads();
        float* tp = hcur; hcur = hnxt; hnxt = tp;

        // dense: out[n][o][t] = dense_b[t][o] + sum_k h[n][k] * dense_W[t][o][k]
        const float* dw = dense_W + (t * C_OUT + oo) * HID;
        const float* hr = hcur + nl;
        float a = __ldg(dense_b + t * C_OUT + oo);
        #pragma unroll 8
        for (int k = 0; k < HID; ++k)
            a = fmaf(hr[k * HS], __ldg(dw + k), a);
        out[((size_t)(n0 + nl) * C_OUT + oo) * T_OUT + t] = a;
        // no sync needed: next step writes the other h buffer; this buffer is
        // only rewritten after the next step's end-of-step barrier.
    }
}

#undef FMA8

// ---------------------------------------------------------------------------
extern "C" void kernel_launch(void* const* d_in, const int* in_sizes, int n_in,
                              void* d_out, int out_size)
{
    (void)in_sizes; (void)n_in; (void)out_size;
    const float* x        = (const float*)d_in[0];
    const float* enc_Wih  = (const float*)d_in[1];
    const float* enc_Whh  = (const float*)d_in[2];
    const float* enc_b    = (const float*)d_in[3];
    const float* dec_Whh  = (const float*)d_in[4];
    const float* dec_b    = (const float*)d_in[5];
    const float* dense_W  = (const float*)d_in[6];
    const float* dense_b  = (const float*)d_in[7];
    float* out = (float*)d_out;

    cudaFuncSetAttribute(lstm_kernel,
                         cudaFuncAttributeMaxDynamicSharedMemorySize, SMEM_BYTES);

    prep_kernel<<<1024, 512>>>(x, enc_Wih, enc_Whh, dec_Whh);
    lstm_kernel<<<128, 512, SMEM_BYTES>>>(enc_b, dec_b, dense_W, dense_b, out);
}

// round 2
// speedup vs baseline: 1.0001x; 1.0001x over previous
#include <cuda_runtime.h>

// ---------------------------------------------------------------------------
// Seq2seq LSTM: encoder (48 steps, C_IN=16) -> decoder (24 steps, zero input)
// -> per-timestep dense H->8.  N=8192, H=256, 4H=1024.
//
// Strategy: batch-parallel persistent CTAs. Each CTA owns 64 samples and runs
// the full recurrence with h (double-buffered) and c in SMEM. Weights are
// pre-transposed to k-major in __device__ scratch so the inner-loop weight
// loads are coalesced across lanes (lane = hidden index k_h). Gate dot
// products use packed fp32x2 FMA (fma.rn.f32x2) over sample pairs.
// ---------------------------------------------------------------------------

#define T_IN   48
#define T_OUT  24
#define C_IN   16
#define C_OUT  8
#define HID    256
#define H4     1024
#define NBATCH 8192

#define NXT (T_IN * C_IN * NBATCH)      // transposed x: [t][c][n]

__device__ float g_xT[NXT];             // ~25 MB scratch
__device__ float g_WihT[C_IN * H4];     // [c][col]   col = gate*256 + k_h
__device__ float g_WhhTe[HID * H4];     // [k][col]
__device__ float g_WhhTd[HID * H4];     // [k][col]

typedef unsigned long long ULL;

// ---- packed f32x2 helpers --------------------------------------------------
__device__ __forceinline__ ULL dup2(float w) {
    ULL r; unsigned u = __float_as_uint(w);
    asm("mov.b64 %0, {%1, %2};" : "=l"(r) : "r"(u), "r"(u));
    return r;
}
__device__ __forceinline__ float2 upk(ULL v) {
    unsigned lo, hi;
    asm("mov.b64 {%0, %1}, %2;" : "=r"(lo), "=r"(hi) : "l"(v));
    return make_float2(__uint_as_float(lo), __uint_as_float(hi));
}
__device__ __forceinline__ ULL f2(ULL a, ULL b, ULL c) {
    ULL d;
    asm("fma.rn.f32x2 %0, %1, %2, %3;" : "=l"(d) : "l"(a), "l"(b), "l"(c));
    return d;
}

// ---- activations (branch-free, safe at extremes) ----------------------------
__device__ __forceinline__ float sigf(float x) {
    return __fdividef(1.0f, 1.0f + __expf(-x));
}
__device__ __forceinline__ float tanh_(float x) {
    return 1.0f - __fdividef(2.0f, __expf(2.0f * x) + 1.0f);
}

// ---- layout constants -------------------------------------------------------
constexpr int HS    = 68;           // padded SMEM row stride (16B aligned, low conflict)
constexpr int HBUF  = HID * HS;     // 17408 floats per h/c buffer
constexpr int SMEM_FLOATS = 3 * HBUF + C_IN * 64;
constexpr int SMEM_BYTES  = SMEM_FLOATS * 4;   // 212992 B

// ---------------------------------------------------------------------------
// Prep: transpose x and the recurrent weights (coalesced writes).
// ---------------------------------------------------------------------------
__global__ void prep_kernel(const float* __restrict__ x,
                            const float* __restrict__ Wih,
                            const float* __restrict__ Whhe,
                            const float* __restrict__ Whhd)
{
    const int TOTAL = NXT + C_IN * H4 + 2 * HID * H4;
    for (int i = blockIdx.x * blockDim.x + threadIdx.x; i < TOTAL;
         i += gridDim.x * blockDim.x) {
        if (i < NXT) {
            int t = i / (C_IN * NBATCH);
            int r = i - t * (C_IN * NBATCH);
            int c = r >> 13;            // / 8192
            int n = r & 8191;
            g_xT[i] = x[(n * C_IN + c) * T_IN + t];
        } else if (i < NXT + C_IN * H4) {
            int j = i - NXT;
            int c = j >> 10, col = j & 1023;
            g_WihT[j] = Wih[col * C_IN + c];
        } else if (i < NXT + C_IN * H4 + HID * H4) {
            int j = i - NXT - C_IN * H4;
            int k = j >> 10, col = j & 1023;
            g_WhhTe[j] = Whhe[col * HID + k];
        } else {
            int j = i - NXT - C_IN * H4 - HID * H4;
            int k = j >> 10, col = j & 1023;
            g_WhhTd[j] = Whhd[col * HID + k];
        }
    }
}

// 8 packed FMAs for one gate row against 4 ulonglong2 (16 samples)
#define FMA8(g, q)                                                   \
    acc[g][0] = f2(q, p0.x, acc[g][0]); acc[g][1] = f2(q, p0.y, acc[g][1]); \
    acc[g][2] = f2(q, p1.x, acc[g][2]); acc[g][3] = f2(q, p1.y, acc[g][3]); \
    acc[g][4] = f2(q, p2.x, acc[g][4]); acc[g][5] = f2(q, p2.y, acc[g][5]); \
    acc[g][6] = f2(q, p3.x, acc[g][6]); acc[g][7] = f2(q, p3.y, acc[g][7]);

// ---------------------------------------------------------------------------
// One LSTM half-pass: this thread computes gates for hidden index k_h and
// 16 samples [bn, bn+16), then does the elementwise LSTM update.
// ---------------------------------------------------------------------------
template <bool WITH_X>
__device__ __forceinline__ void lstm_pass(
    const float* __restrict__ wh,      // transposed Whh [k][col]
    const float* __restrict__ bias,    // (4H,)
    const float* __restrict__ hcur, float* __restrict__ hnxt,
    float* __restrict__ cs, const float* __restrict__ xs,
    int k_h, int bn)
{
    ULL acc[4][8];
    {
        ULL bi = dup2(__ldg(bias + k_h));
        ULL bf = dup2(__ldg(bias + 256 + k_h));
        ULL bg = dup2(__ldg(bias + 512 + k_h));
        ULL bo = dup2(__ldg(bias + 768 + k_h));
        #pragma unroll
        for (int i = 0; i < 8; ++i) {
            acc[0][i] = bi; acc[1][i] = bf; acc[2][i] = bg; acc[3][i] = bo;
        }
    }

    if (WITH_X) {
        const float* wr = g_WihT + k_h;
        const float* xr = xs + bn;
        #pragma unroll
        for (int c2 = 0; c2 < C_IN; ++c2) {
            float w0 = wr[0], w1 = wr[256], w2 = wr[512], w3 = wr[768];
            const ulonglong2* xp = reinterpret_cast<const ulonglong2*>(xr);
            ulonglong2 p0 = xp[0], p1 = xp[1], p2 = xp[2], p3 = xp[3];
            ULL q0 = dup2(w0), q1 = dup2(w1), q2 = dup2(w2), q3 = dup2(w3);
            FMA8(0, q0) FMA8(1, q1) FMA8(2, q2) FMA8(3, q3)
            wr += H4; xr += 64;
        }
    }

    const float* wr = wh + k_h;
    const float* hr = hcur + bn;
    #pragma unroll 2
    for (int k = 0; k < HID; ++k) {
        float w0 = __ldg(wr), w1 = __ldg(wr + 256),
              w2 = __ldg(wr + 512), w3 = __ldg(wr + 768);
        const ulonglong2* hp = reinterpret_cast<const ulonglong2*>(hr);
        ulonglong2 p0 = hp[0], p1 = hp[1], p2 = hp[2], p3 = hp[3];
        ULL q0 = dup2(w0), q1 = dup2(w1), q2 = dup2(w2), q3 = dup2(w3);
        FMA8(0, q0) FMA8(1, q1) FMA8(2, q2) FMA8(3, q3)
        wr += H4; hr += HS;
    }

    // elementwise LSTM update (this thread exclusively owns (k_h, n) cells)
    #pragma unroll
    for (int i = 0; i < 8; ++i) {
        float2 vi = upk(acc[0][i]), vf = upk(acc[1][i]);
        float2 vg = upk(acc[2][i]), vo = upk(acc[3][i]);
        int idx = k_h * HS + bn + 2 * i;
        {
            float co = cs[idx];
            float cn = sigf(vf.x) * co + sigf(vi.x) * tanh_(vg.x);
            cs[idx]   = cn;
            hnxt[idx] = sigf(vo.x) * tanh_(cn);
        }
        {
            float co = cs[idx + 1];
            float cn = sigf(vf.y) * co + sigf(vi.y) * tanh_(vg.y);
            cs[idx + 1]   = cn;
            hnxt[idx + 1] = sigf(vo.y) * tanh_(cn);
        }
    }
}

// ---------------------------------------------------------------------------
// Main persistent kernel: 128 CTAs x 512 threads, 64 samples per CTA.
// ---------------------------------------------------------------------------
__global__ void __launch_bounds__(512, 1)
lstm_kernel(const float* __restrict__ enc_b, const float* __restrict__ dec_b,
            const float* __restrict__ dense_W, const float* __restrict__ dense_b,
            float* __restrict__ out)
{
    extern __shared__ float smem[];
    float* hA = smem;
    float* hB = smem + HBUF;
    float* cs = smem + 2 * HBUF;
    float* xs = smem + 3 * HBUF;

    const int tid = threadIdx.x;
    const int k_h = tid & 255;
    const int nh  = tid >> 8;          // 0 or 1: sample half
    const int n0  = blockIdx.x * 64;

    for (int i = tid; i < 3 * HBUF; i += 512) smem[i] = 0.0f;
    __syncthreads();

    float* hcur = hA;
    float* hnxt = hB;

    // -------- encoder --------
    for (int t = 0; t < T_IN; ++t) {
        for (int i = tid; i < C_IN * 64; i += 512)
            xs[i] = g_xT[(t * C_IN + (i >> 6)) * NBATCH + n0 + (i & 63)];
        __syncthreads();
        lstm_pass<true>(g_WhhTe, enc_b, hcur, hnxt, cs, xs, k_h, nh * 32);
        lstm_pass<true>(g_WhhTe, enc_b, hcur, hnxt, cs, xs, k_h, nh * 32 + 16);
        __syncthreads();
        float* tp = hcur; hcur = hnxt; hnxt = tp;
    }

    // decoder starts from (h_enc, c = 0)
    for (int i = tid; i < HBUF; i += 512) cs[i] = 0.0f;
    __syncthreads();

    // -------- decoder + per-timestep dense --------
    const int nl = tid & 63;
    const int oo = tid >> 6;           // 0..7
    for (int t = 0; t < T_OUT; ++t) {
        lstm_pass<false>(g_WhhTd, dec_b, hcur, hnxt, cs, nullptr, k_h, nh * 32);
        lstm_pass<false>(g_WhhTd, dec_b, hcur, hnxt, cs, nullptr, k_h, nh * 32 + 16);
        __syncthreads();
        float* tp = hcur; hcur = hnxt; hnxt = tp;

        // dense: out[n][o][t] = dense_b[t][o] + sum_k h[n][k] * dense_W[t][o][k]
        const float* dw = dense_W + (t * C_OUT + oo) * HID;
        const float* hr = hcur + nl;
        float a = __ldg(dense_b + t * C_OUT + oo);
        #pragma unroll 8
        for (int k = 0; k < HID; ++k)
            a = fmaf(hr[k * HS], __ldg(dw + k), a);
        out[((size_t)(n0 + nl) * C_OUT + oo) * T_OUT + t] = a;
        // no sync needed: next step writes the other h buffer; this buffer is
        // only rewritten after the next step's end-of-step barrier.
    }
}

#undef FMA8

// ---------------------------------------------------------------------------
extern "C" void kernel_launch(void* const* d_in, const int* in_sizes, int n_in,
                              void* d_out, int out_size)
{
    (void)in_sizes; (void)n_in; (void)out_size;
    const float* x        = (const float*)d_in[0];
    const float* enc_Wih  = (const float*)d_in[1];
    const float* enc_Whh  = (const float*)d_in[2];
    const float* enc_b    = (const float*)d_in[3];
    const float* dec_Whh  = (const float*)d_in[4];
    const float* dec_b    = (const float*)d_in[5];
    const float* dense_W  = (const float*)d_in[6];
    const float* dense_b  = (const float*)d_in[7];
    float* out = (float*)d_out;

    cudaFuncSetAttribute(lstm_kernel,
                         cudaFuncAttributeMaxDynamicSharedMemorySize, SMEM_BYTES);

    prep_kernel<<<1024, 512>>>(x, enc_Wih, enc_Whh, dec_Whh);
    lstm_kernel<<<128, 512, SMEM_BYTES>>>(enc_b, dec_b, dense_W, dense_b, out);
}